// round 7
// baseline (speedup 1.0000x reference)
#include <cuda_runtime.h>
#include <cstdint>

// ============================================================================
// FlattenedObsEncoder: out[16384,1024] = (gather(W_embed,x)+b_embed) @ W_dense + b_dense
// tf32 mma.sync GEMM (base sm_103 ptxas target -> HMMA path).
// CTA tile 128x128, 256 threads (8 warps, warp tile 32x64), 2 CTAs/SM,
// 3-stage cp.async pipeline for B, in-loop A gather.
// R7: ldmatrix.x4 A-fragments + register double-buffered frag pipeline.
// ============================================================================

#define B_SZ   16384
#define P_SZ   256
#define K_SZ   1024
#define N_SZ   1024
#define MT     128
#define NT     128
#define KC     32
#define NCHUNK (K_SZ / KC)    // 32
#define THREADS 256
#define SA     36                    // A smem row stride (floats)
#define A_ST   (MT * SA)             // 4608 floats
#define B_ST   (NT * KC)             // 4096 floats (fragment-packed)
#define STAGE_F (A_ST + B_ST)        // 8704 floats
#define NSTAGE 3
#define SMEM_BYTES (STAGE_F * NSTAGE * 4)   // 104,448 B -> 2 CTAs/SM

// W_dense permuted into HMMA B-fragment order, tf32-rounded:
// float index = nb*16384 + ks*128 + (g*4+t4)*4 + jj*2 + h
//   where n = nb*16 + jj*8 + g,  k = ks*8 + t4 + 4*h
__device__ float g_WdT[(size_t)N_SZ * K_SZ];

// ---------------------------------------------------------------------------
__device__ __forceinline__ uint32_t smem_u32(const void* p) {
    uint32_t a;
    asm("{ .reg .u64 t; cvta.to.shared.u64 t, %1; cvt.u32.u64 %0, t; }" : "=r"(a) : "l"(p));
    return a;
}
__device__ __forceinline__ float tf32_rn(float v) {
    float r;
    asm("cvt.rna.tf32.f32 %0, %1;" : "=f"(r) : "f"(v));
    return r;
}
__device__ __forceinline__ void cp16(uint32_t s, const void* g) {
    asm volatile("cp.async.cg.shared.global [%0], [%1], 16;" :: "r"(s), "l"(g));
}
#define CP_COMMIT() asm volatile("cp.async.commit_group;" ::: "memory")
#define CP_WAIT1()  asm volatile("cp.async.wait_group 1;" ::: "memory")

// ---------------------------------------------------------------------------
// Prepass: permute W_dense [K,N] into fragment order + tf32 round.
// ---------------------------------------------------------------------------
__global__ void pack_wd_kernel(const float* __restrict__ Wd) {
    const int n = blockIdx.x * 256 + threadIdx.x;
    const int k = blockIdx.y;
    const float v = tf32_rn(Wd[(size_t)k * N_SZ + n]);
    const int nb = n >> 4, jj = (n >> 3) & 1, g = n & 7;
    const int ks = k >> 3, kk = k & 7, t4 = kk & 3, h = kk >> 2;
    g_WdT[(size_t)nb * 16384 + ks * 128 + (g * 4 + t4) * 4 + jj * 2 + h] = v;
}

// ---------------------------------------------------------------------------
// Fragment loads
// ---------------------------------------------------------------------------
__device__ __forceinline__ void ldsm_a(uint32_t addr0, uint32_t addr1, uint32_t a[8]) {
    asm volatile("ldmatrix.sync.aligned.m8n8.x4.shared.b16 {%0,%1,%2,%3}, [%4];"
                 : "=r"(a[0]), "=r"(a[1]), "=r"(a[2]), "=r"(a[3]) : "r"(addr0));
    asm volatile("ldmatrix.sync.aligned.m8n8.x4.shared.b16 {%0,%1,%2,%3}, [%4];"
                 : "=r"(a[4]), "=r"(a[5]), "=r"(a[6]), "=r"(a[7]) : "r"(addr1));
}
__device__ __forceinline__ void lds_b(const float* p, float4 b[4]) {
#pragma unroll
    for (int i = 0; i < 4; ++i)
        b[i] = *(const float4*)(p + i * 512);
}

__device__ __forceinline__ void mma_all(const uint32_t a[8], const float4 b[4],
                                        float c[2][8][4]) {
#pragma unroll
    for (int i4 = 0; i4 < 4; ++i4) {
        const uint32_t b00 = __float_as_uint(b[i4].x), b01 = __float_as_uint(b[i4].y);
        const uint32_t b10 = __float_as_uint(b[i4].z), b11 = __float_as_uint(b[i4].w);
#pragma unroll
        for (int i = 0; i < 2; ++i) {
            asm volatile(
                "mma.sync.aligned.m16n8k8.row.col.f32.tf32.tf32.f32 "
                "{%0,%1,%2,%3}, {%4,%5,%6,%7}, {%8,%9}, {%0,%1,%2,%3};"
                : "+f"(c[i][i4 * 2][0]), "+f"(c[i][i4 * 2][1]),
                  "+f"(c[i][i4 * 2][2]), "+f"(c[i][i4 * 2][3])
                : "r"(a[i * 4 + 0]), "r"(a[i * 4 + 1]), "r"(a[i * 4 + 2]), "r"(a[i * 4 + 3]),
                  "r"(b00), "r"(b01));
            asm volatile(
                "mma.sync.aligned.m16n8k8.row.col.f32.tf32.tf32.f32 "
                "{%0,%1,%2,%3}, {%4,%5,%6,%7}, {%8,%9}, {%0,%1,%2,%3};"
                : "+f"(c[i][i4 * 2 + 1][0]), "+f"(c[i][i4 * 2 + 1][1]),
                  "+f"(c[i][i4 * 2 + 1][2]), "+f"(c[i][i4 * 2 + 1][3])
                : "r"(a[i * 4 + 0]), "r"(a[i * 4 + 1]), "r"(a[i * 4 + 2]), "r"(a[i * 4 + 3]),
                  "r"(b10), "r"(b11));
        }
    }
}

// ---------------------------------------------------------------------------
// Main GEMM kernel.  SMEM: 3 stages of [A: MT x SA | B packed: 4096 floats].
// ---------------------------------------------------------------------------
__global__ void __launch_bounds__(THREADS, 2)
enc_gemm_kernel(const int* __restrict__ x, const float* __restrict__ We,
                const float* __restrict__ be, const float* __restrict__ bd,
                float* __restrict__ out) {
    extern __shared__ float smem[];
    const uint32_t sbase = smem_u32(smem);

    const int tid = threadIdx.x;
    const int wid = tid >> 5, lane = tid & 31;
    const int g = lane >> 2, t4 = lane & 3;
    const int warp_m = wid & 3;      // 4 x 32 = 128 M
    const int warp_n = wid >> 2;     // 2 x 64 = 128 N
    const int n0 = blockIdx.x * NT;
    const int m0 = blockIdx.y * MT;

    // ldmatrix per-lane source row/col within the A tile
    const int lrow = warp_m * 32 + (lane & 7) + ((lane >> 3) & 1) * 8;
    const int lcol = (lane >> 4) * 4;
    const uint32_t aFragOff = (uint32_t)(lrow * SA + lcol) * 4u;

    // A-gather mapping: 2 threads per M row, 4 positions (16 floats) each.
    const int arow = tid >> 1, ahalf = tid & 1;
    const int* xptr = x + (size_t)(m0 + arow) * P_SZ + ahalf * 4;
    const float4* We4 = (const float4*)We;
    const float be0 = be[0], be1 = be[1], be2 = be[2], be3 = be[3];
    const uint32_t aDstOff = (uint32_t)arow * (SA * 4u) + (uint32_t)ahalf * 64u;

    // B-copy: 1024 x 16B per chunk / 256 threads = 4 each.
    const float* bsrc = g_WdT + (size_t)(n0 >> 4) * 16384;

    float c[2][8][4];
#pragma unroll
    for (int i = 0; i < 2; ++i)
#pragma unroll
        for (int j = 0; j < 8; ++j)
#pragma unroll
            for (int q = 0; q < 4; ++q) c[i][j][q] = 0.0f;

    auto stageB = [&](int s) -> const float* { return smem + (size_t)s * STAGE_F + A_ST; };
    auto stageAaddr = [&](int s) -> uint32_t { return sbase + (uint32_t)s * (STAGE_F * 4u); };
    auto stageBaddr = [&](int s) -> uint32_t { return sbase + (uint32_t)s * (STAGE_F * 4u) + A_ST * 4u; };

    auto copyB = [&](int ch, int s) {
        const uint32_t bA = stageBaddr(s);
        const float* src = bsrc + (size_t)ch * 512;
#pragma unroll
        for (int i = 0; i < 4; ++i) {
            const int cc = tid * 4 + i;
            const int nb = cc >> 7, rem = cc & 127;
            cp16(bA + (uint32_t)nb * 2048u + (uint32_t)rem * 16u,
                 src + (size_t)nb * 16384 + rem * 4);
        }
    };
    auto stsA = [&](int s, int p, float4 e) {
        const uint32_t vx = __float_as_uint(tf32_rn(e.x + be0));
        const uint32_t vy = __float_as_uint(tf32_rn(e.y + be1));
        const uint32_t vz = __float_as_uint(tf32_rn(e.z + be2));
        const uint32_t vw = __float_as_uint(tf32_rn(e.w + be3));
        asm volatile("st.shared.v4.b32 [%0], {%1,%2,%3,%4};"
                     :: "r"(stageAaddr(s) + aDstOff + (uint32_t)p * 16u),
                        "r"(vx), "r"(vy), "r"(vz), "r"(vw) : "memory");
    };
    auto gatherA = [&](int ch, int s) {
        const int4 xi = *(const int4*)(xptr + ch * 8);
        stsA(s, 0, __ldg(We4 + xi.x));
        stsA(s, 1, __ldg(We4 + xi.y));
        stsA(s, 2, __ldg(We4 + xi.z));
        stsA(s, 3, __ldg(We4 + xi.w));
    };

    // ---- prologue ----
    gatherA(0, 0);
    copyB(0, 0); CP_COMMIT();
    copyB(1, 1); CP_COMMIT();

    uint32_t afA[8], afB[8];
    float4   bfA[4], bfB[4];

    // ---- mainloop ----
    for (int ch = 0; ch < NCHUNK; ++ch) {
        const int st = ch % 3;
        const bool more = (ch + 1 < NCHUNK);

        CP_WAIT1();              // B(ch) landed
        __syncthreads();         // A(ch) visible; stage (ch+2)%3 free

        if (ch + 2 < NCHUNK) copyB(ch + 2, (ch + 2) % 3);
        CP_COMMIT();

        const uint32_t aAddr = stageAaddr(st) + aFragOff;       // + ks*32
        const float*   bPtr  = stageB(st) + warp_n * 2048 + lane * 4;  // + ks*128

        // kstep 0 frags
        ldsm_a(aAddr, aAddr + 16u * SA * 4u, afA);
        lds_b(bPtr, bfA);

        int4 xi = {0, 0, 0, 0};
        if (more) xi = *(const int4*)(xptr + (ch + 1) * 8);

        // ks=1 frags, then MMA(0)
        ldsm_a(aAddr + 32u, aAddr + 16u * SA * 4u + 32u, afB);
        lds_b(bPtr + 128, bfB);
        mma_all(afA, bfA, c);

        // gather next chunk's A (LDG -> STS immediately; stage (ch+1)%3)
        if (more) {
            const int ns = (ch + 1) % 3;
            stsA(ns, 0, __ldg(We4 + xi.x));
            stsA(ns, 1, __ldg(We4 + xi.y));
            stsA(ns, 2, __ldg(We4 + xi.z));
            stsA(ns, 3, __ldg(We4 + xi.w));
        }

        // ks=2 frags, MMA(1)
        ldsm_a(aAddr + 64u, aAddr + 16u * SA * 4u + 64u, afA);
        lds_b(bPtr + 256, bfA);
        mma_all(afB, bfB, c);

        // ks=3 frags, MMA(2)
        ldsm_a(aAddr + 96u, aAddr + 16u * SA * 4u + 96u, afB);
        lds_b(bPtr + 384, bfB);
        mma_all(afA, bfA, c);

        // MMA(3)
        mma_all(afB, bfB, c);
    }

    // ---- epilogue: accum + b_dense -> out ----
#pragma unroll
    for (int i = 0; i < 2; ++i) {
        const size_t r0 = (size_t)(m0 + warp_m * 32 + i * 16 + g);
#pragma unroll
        for (int j = 0; j < 8; ++j) {
            const int col = n0 + warp_n * 64 + j * 8 + t4 * 2;
            const float2 bb = *(const float2*)(bd + col);
            float2 v0, v1;
            v0.x = c[i][j][0] + bb.x;  v0.y = c[i][j][1] + bb.y;
            v1.x = c[i][j][2] + bb.x;  v1.y = c[i][j][3] + bb.y;
            *(float2*)(out + r0 * N_SZ + col)       = v0;
            *(float2*)(out + (r0 + 8) * N_SZ + col) = v1;
        }
    }
}

// ---------------------------------------------------------------------------
// kernel_launch
// ---------------------------------------------------------------------------
extern "C" void kernel_launch(void* const* d_in, const int* in_sizes, int n_in,
                              void* d_out, int out_size) {
    const int*   x  = (const int*)d_in[0];
    const float* We = (const float*)d_in[1];
    const float* be = (const float*)d_in[2];
    const float* Wd = (const float*)d_in[3];
    const float* bd = (const float*)d_in[4];
    float* out = (float*)d_out;

    cudaStreamCaptureStatus cs = cudaStreamCaptureStatusNone;
    cudaError_t qerr = cudaStreamIsCapturing((cudaStream_t)0, &cs);
    const bool capturing = (qerr != cudaSuccess) || (cs != cudaStreamCaptureStatusNone);
    if (!capturing) {
        cudaFuncSetAttribute(enc_gemm_kernel,
                             cudaFuncAttributeMaxDynamicSharedMemorySize, SMEM_BYTES);
    }
    (void)cudaGetLastError();

    pack_wd_kernel<<<dim3(N_SZ / 256, K_SZ), 256>>>(Wd);
    enc_gemm_kernel<<<dim3(N_SZ / NT, B_SZ / MT), THREADS, SMEM_BYTES>>>(x, We, be, bd, out);
}

// round 8
// speedup vs baseline: 1.2639x; 1.2639x over previous
#include <cuda_runtime.h>
#include <cstdint>

// ============================================================================
// FlattenedObsEncoder: out[16384,1024] = (gather(W_embed,x)+b_embed) @ W_dense + b_dense
// tf32 mma.sync GEMM (base sm_103 ptxas target -> HMMA path).
// R8: A gathered ONCE by a prepass into HMMA-fragment-packed gmem; mainloop is
// a pure dense GEMM (cp.async A+B, LDS.128 frags, HMMA).  CTA 128x128,
// 256 threads, warp tile 32x64, 2 CTAs/SM, 3-stage pipeline.
// ============================================================================

#define B_SZ   16384
#define P_SZ   256
#define K_SZ   1024
#define N_SZ   1024
#define NCLS   1024
#define MT     128
#define NT     128
#define KC     32
#define NCHUNK (K_SZ / KC)    // 32
#define THREADS 256
#define A_ST   (MT * KC)             // 4096 floats (fragment-packed)
#define B_ST   (NT * KC)             // 4096 floats (fragment-packed)
#define STAGE_F (A_ST + B_ST)        // 8192 floats
#define NSTAGE 3
#define SMEM_BYTES (STAGE_F * NSTAGE * 4)   // 98,304 B -> 2 CTAs/SM

// B: W_dense permuted into HMMA B-fragment order, tf32-rounded:
//   idx = nb*16384 + ksg*128 + (g*4+t4)*4 + jj*2 + h
//   where n = nb*16 + jj*8 + g,  k = ksg*8 + t4 + 4*h        (ksg = global kstep)
__device__ float g_WdT[(size_t)N_SZ * K_SZ];

// A: gather(W_embed,x)+b_embed, tf32-rounded, HMMA a-fragment order:
//   idx = ((size_t)mb*32 + ch)*512 + ksl*128 + lane*4 + q
//   lane=(g,t4): q0=A[mb*16+g][k], q1=A[mb*16+8+g][k], q2=A[..g][k+4], q3=A[..8+g][k+4]
//   with k = (ch*4+ksl)*8 + t4
__device__ float g_Apack[(size_t)B_SZ * K_SZ];

// ---------------------------------------------------------------------------
__device__ __forceinline__ uint32_t smem_u32(const void* p) {
    uint32_t a;
    asm("{ .reg .u64 t; cvta.to.shared.u64 t, %1; cvt.u32.u64 %0, t; }" : "=r"(a) : "l"(p));
    return a;
}
__device__ __forceinline__ float tf32_rn(float v) {
    float r;
    asm("cvt.rna.tf32.f32 %0, %1;" : "=f"(r) : "f"(v));
    return r;
}
__device__ __forceinline__ void cp16(uint32_t s, const void* g) {
    asm volatile("cp.async.cg.shared.global [%0], [%1], 16;" :: "r"(s), "l"(g));
}
#define CP_COMMIT() asm volatile("cp.async.commit_group;" ::: "memory")
#define CP_WAIT1()  asm volatile("cp.async.wait_group 1;" ::: "memory")

// ---------------------------------------------------------------------------
// Prepass 1: permute W_dense [K,N] into fragment order + tf32 round.
// ---------------------------------------------------------------------------
__global__ void pack_wd_kernel(const float* __restrict__ Wd) {
    const int n = blockIdx.x * 256 + threadIdx.x;
    const int k = blockIdx.y;
    const float v = tf32_rn(Wd[(size_t)k * N_SZ + n]);
    const int nb = n >> 4, jj = (n >> 3) & 1, g = n & 7;
    const int ks = k >> 3, kk = k & 7, t4 = kk & 3, h = kk >> 2;
    g_WdT[(size_t)nb * 16384 + ks * 128 + (g * 4 + t4) * 4 + jj * 2 + h] = v;
}

// ---------------------------------------------------------------------------
// Prepass 2: gather + bias + tf32 round into fragment-packed A.
// One block per 128 M-rows; W_embed staged in SMEM (scattered LDS, cheap).
// ---------------------------------------------------------------------------
__global__ void __launch_bounds__(256)
pack_a_kernel(const int* __restrict__ x, const float* __restrict__ We,
              const float* __restrict__ be) {
    __shared__ float sWe[NCLS * 4];   // 16 KB
    __shared__ float sbe[4];
    for (int i = threadIdx.x; i < NCLS * 4; i += 256) sWe[i] = We[i];
    if (threadIdx.x < 4) sbe[threadIdx.x] = be[threadIdx.x];
    __syncthreads();

    const int tid = threadIdx.x;
    const int lane = tid & 31, w = tid >> 5;      // 8 warps cover ks mod 8
    const int g = lane >> 2, t4 = lane & 3;
    const float bt = sbe[t4];
    const int rowbase = blockIdx.x * 128;

#pragma unroll 2
    for (int mb_l = 0; mb_l < 8; ++mb_l) {
        const int r0 = rowbase + mb_l * 16 + g;
        const int* x0 = x + (size_t)r0 * P_SZ;
        const int* x1 = x + (size_t)(r0 + 8) * P_SZ;
        const size_t mb = (size_t)(rowbase >> 4) + mb_l;
#pragma unroll 4
        for (int kk = 0; kk < 16; ++kk) {
            const int ks = kk * 8 + w;            // global kstep 0..127
            const int p0 = ks * 2;
            const int2 xa = *(const int2*)(x0 + p0);
            const int2 xb = *(const int2*)(x1 + p0);
            float4 v;
            v.x = tf32_rn(sWe[xa.x * 4 + t4] + bt);
            v.y = tf32_rn(sWe[xb.x * 4 + t4] + bt);
            v.z = tf32_rn(sWe[xa.y * 4 + t4] + bt);
            v.w = tf32_rn(sWe[xb.y * 4 + t4] + bt);
            *(float4*)(g_Apack + (mb * 32 + (ks >> 2)) * 512
                       + (ks & 3) * 128 + lane * 4) = v;
        }
    }
}

// ---------------------------------------------------------------------------
// MMA helper: one kstep = 32 HMMAs from packed fragments.
// ---------------------------------------------------------------------------
__device__ __forceinline__ void mma_kstep(const float4 a[2], const float4 b[4],
                                          float c[2][8][4]) {
#pragma unroll
    for (int i4 = 0; i4 < 4; ++i4) {
        const uint32_t b00 = __float_as_uint(b[i4].x), b01 = __float_as_uint(b[i4].y);
        const uint32_t b10 = __float_as_uint(b[i4].z), b11 = __float_as_uint(b[i4].w);
#pragma unroll
        for (int i = 0; i < 2; ++i) {
            const uint32_t a0 = __float_as_uint(a[i].x), a1 = __float_as_uint(a[i].y);
            const uint32_t a2 = __float_as_uint(a[i].z), a3 = __float_as_uint(a[i].w);
            asm volatile(
                "mma.sync.aligned.m16n8k8.row.col.f32.tf32.tf32.f32 "
                "{%0,%1,%2,%3}, {%4,%5,%6,%7}, {%8,%9}, {%0,%1,%2,%3};"
                : "+f"(c[i][i4 * 2][0]), "+f"(c[i][i4 * 2][1]),
                  "+f"(c[i][i4 * 2][2]), "+f"(c[i][i4 * 2][3])
                : "r"(a0), "r"(a1), "r"(a2), "r"(a3), "r"(b00), "r"(b01));
            asm volatile(
                "mma.sync.aligned.m16n8k8.row.col.f32.tf32.tf32.f32 "
                "{%0,%1,%2,%3}, {%4,%5,%6,%7}, {%8,%9}, {%0,%1,%2,%3};"
                : "+f"(c[i][i4 * 2 + 1][0]), "+f"(c[i][i4 * 2 + 1][1]),
                  "+f"(c[i][i4 * 2 + 1][2]), "+f"(c[i][i4 * 2 + 1][3])
                : "r"(a0), "r"(a1), "r"(a2), "r"(a3), "r"(b10), "r"(b11));
        }
    }
}

// ---------------------------------------------------------------------------
// Main GEMM.  SMEM: 3 stages of [A packed 4096 | B packed 4096] floats.
// ---------------------------------------------------------------------------
__global__ void __launch_bounds__(THREADS, 2)
enc_gemm_kernel(const float* __restrict__ bd, float* __restrict__ out) {
    extern __shared__ float smem[];
    const uint32_t sbase = smem_u32(smem);

    const int tid = threadIdx.x;
    const int wid = tid >> 5, lane = tid & 31;
    const int g = lane >> 2, t4 = lane & 3;
    const int warp_m = wid & 3;      // 4 x 32 = 128 M
    const int warp_n = wid >> 2;     // 2 x 64 = 128 N
    const int n0 = blockIdx.x * NT;
    const int m0 = blockIdx.y * MT;

    const float* asrc = g_Apack + ((size_t)(m0 >> 4) * 32) * 512;  // + mb*32*512
    const float* bsrc = g_WdT + (size_t)(n0 >> 4) * 16384;

    float c[2][8][4];
#pragma unroll
    for (int i = 0; i < 2; ++i)
#pragma unroll
        for (int j = 0; j < 8; ++j)
#pragma unroll
            for (int q = 0; q < 4; ++q) c[i][j][q] = 0.0f;

    auto stageAf = [&](int s) -> const float* { return smem + (size_t)s * STAGE_F; };
    auto stageBf = [&](int s) -> const float* { return smem + (size_t)s * STAGE_F + A_ST; };
    auto stageAaddr = [&](int s) -> uint32_t { return sbase + (uint32_t)s * (STAGE_F * 4u); };
    auto stageBaddr = [&](int s) -> uint32_t { return sbase + (uint32_t)s * (STAGE_F * 4u) + A_ST * 4u; };

    // per-chunk copies: A 1024 cp16 + B 1024 cp16 over 256 threads = 4+4 each
    auto copyAB = [&](int ch, int s) {
        const uint32_t aA = stageAaddr(s), bA = stageBaddr(s);
        const float* asr = asrc + (size_t)ch * 512;    // + mb*32*512
        const float* bsr = bsrc + (size_t)ch * 512;    // + nb*16384
#pragma unroll
        for (int i = 0; i < 4; ++i) {
            const int cc = i * 256 + tid;
            const int mb = cc >> 7, rem = cc & 127;
            cp16(aA + (uint32_t)mb * 2048u + (uint32_t)rem * 16u,
                 asr + (size_t)mb * 16384 + rem * 4);
        }
#pragma unroll
        for (int i = 0; i < 4; ++i) {
            const int cc = i * 256 + tid;
            const int nb = cc >> 7, rem = cc & 127;
            cp16(bA + (uint32_t)nb * 2048u + (uint32_t)rem * 16u,
                 bsr + (size_t)nb * 16384 + rem * 4);
        }
    };

    // ---- prologue ----
    copyAB(0, 0); CP_COMMIT();
    copyAB(1, 1); CP_COMMIT();

    // ---- mainloop ----
    for (int ch = 0; ch < NCHUNK; ++ch) {
        const int st = ch % 3;

        CP_WAIT1();              // stage st landed
        __syncthreads();         // stage (ch+2)%3 free

        if (ch + 2 < NCHUNK) copyAB(ch + 2, (ch + 2) % 3);
        CP_COMMIT();

        // A frags: warp_m covers mb {2*warp_m, 2*warp_m+1}
        const float* aPtr = stageAf(st) + (warp_m * 2) * 512 + lane * 4;   // + i*512 + ksl*128
        const float* bPtr = stageBf(st) + warp_n * 2048 + lane * 4;        // + i4*512 + ksl*128

#pragma unroll
        for (int ksl = 0; ksl < 4; ++ksl) {
            float4 a[2], b[4];
            a[0] = *(const float4*)(aPtr + ksl * 128);
            a[1] = *(const float4*)(aPtr + 512 + ksl * 128);
#pragma unroll
            for (int i = 0; i < 4; ++i)
                b[i] = *(const float4*)(bPtr + i * 512 + ksl * 128);
            mma_kstep(a, b, c);
        }
    }

    // ---- epilogue: accum + b_dense -> out ----
#pragma unroll
    for (int i = 0; i < 2; ++i) {
        const size_t r0 = (size_t)(m0 + warp_m * 32 + i * 16 + g);
#pragma unroll
        for (int j = 0; j < 8; ++j) {
            const int col = n0 + warp_n * 64 + j * 8 + t4 * 2;
            const float2 bb = *(const float2*)(bd + col);
            float2 v0, v1;
            v0.x = c[i][j][0] + bb.x;  v0.y = c[i][j][1] + bb.y;
            v1.x = c[i][j][2] + bb.x;  v1.y = c[i][j][3] + bb.y;
            *(float2*)(out + r0 * N_SZ + col)       = v0;
            *(float2*)(out + (r0 + 8) * N_SZ + col) = v1;
        }
    }
}

// ---------------------------------------------------------------------------
// kernel_launch
// ---------------------------------------------------------------------------
extern "C" void kernel_launch(void* const* d_in, const int* in_sizes, int n_in,
                              void* d_out, int out_size) {
    const int*   x  = (const int*)d_in[0];
    const float* We = (const float*)d_in[1];
    const float* be = (const float*)d_in[2];
    const float* Wd = (const float*)d_in[3];
    const float* bd = (const float*)d_in[4];
    float* out = (float*)d_out;

    cudaStreamCaptureStatus cs = cudaStreamCaptureStatusNone;
    cudaError_t qerr = cudaStreamIsCapturing((cudaStream_t)0, &cs);
    const bool capturing = (qerr != cudaSuccess) || (cs != cudaStreamCaptureStatusNone);
    if (!capturing) {
        cudaFuncSetAttribute(enc_gemm_kernel,
                             cudaFuncAttributeMaxDynamicSharedMemorySize, SMEM_BYTES);
    }
    (void)cudaGetLastError();

    pack_wd_kernel<<<dim3(N_SZ / 256, K_SZ), 256>>>(Wd);
    pack_a_kernel<<<B_SZ / 128, 256>>>(x, We, be);
    enc_gemm_kernel<<<dim3(N_SZ / NT, B_SZ / MT), THREADS, SMEM_BYTES>>>(bd, out);
}

// round 11
// speedup vs baseline: 2.5211x; 1.9946x over previous
#include <cuda_runtime.h>
#include <cuda_fp16.h>
#include <cstdint>
#include <cstring>

// ============================================================================
// FlattenedObsEncoder: out[16384,1024] = (gather(W_embed,x)+b_embed) @ W_dense + b_dense
// fp16 m16n8k16 mma.sync GEMM with fp32 accumulation (same 11-bit significand
// as tf32 -> same ~3e-4 rel_err, half the HMMA instructions).
// A and B pre-packed into exact HMMA fragment order by prepasses.
// CTA 128x128, 256 threads, warp tile 32x64, 2 CTAs/SM, 3-stage pipeline.
// ============================================================================

#define B_SZ   16384
#define P_SZ   256
#define K_SZ   1024
#define N_SZ   1024
#define NCLS   1024
#define MT     128
#define NT     128
#define NKS    (K_SZ / 16)    // 64 global k16-steps
#define KSC    4              // ksteps per chunk
#define NCHUNK (NKS / KSC)    // 16
#define THREADS 256
// stage: A 8 mb x 4 ks x 32 lanes uint4 = 1024 u4; B same
#define A_U4   1024
#define B_U4   1024
#define STAGE_U4 (A_U4 + B_U4)               // 2048 uint4 = 32 KB
#define NSTAGE 3
#define SMEM_BYTES (STAGE_U4 * NSTAGE * 16)  // 98,304 B -> 2 CTAs/SM

// B fragments: uint4 index = (nb16*NKS + ks)*32 + lane
//   lane (g = lane>>2, t4 = lane&3):
//   .x={B[k0][n0+g],B[k0+1][n0+g]} .y={B[k0+8][..],B[k0+9][..]}  (n-tile jj=0)
//   .z,.w same with n0+8                                        (n-tile jj=1)
//   k0 = ks*16 + 2*t4, n0 = nb16*16
__device__ uint4 g_Bpack[(size_t)(N_SZ / 16) * NKS * 32];

// A fragments: uint4 index = (mb*NKS + ks)*32 + lane
//   .x={A[r][k0],A[r][k0+1]} .y={A[r+8][k0],A[r+8][k0+1]}
//   .z={A[r][k0+8],A[r][k0+9]} .w={A[r+8][k0+8],A[r+8][k0+9]}
//   r = mb*16 + g, k0 = ks*16 + 2*t4
__device__ uint4 g_Apack[(size_t)(B_SZ / 16) * NKS * 32];

// ---------------------------------------------------------------------------
__device__ __forceinline__ uint32_t smem_u32(const void* p) {
    uint32_t a;
    asm("{ .reg .u64 t; cvta.to.shared.u64 t, %1; cvt.u32.u64 %0, t; }" : "=r"(a) : "l"(p));
    return a;
}
__device__ __forceinline__ void cp16(uint32_t s, const void* g) {
    asm volatile("cp.async.cg.shared.global [%0], [%1], 16;" :: "r"(s), "l"(g));
}
#define CP_COMMIT() asm volatile("cp.async.commit_group;" ::: "memory")
#define CP_WAIT1()  asm volatile("cp.async.wait_group 1;" ::: "memory")

__device__ __forceinline__ uint32_t h2pack(float lo, float hi) {
    const __half2 h = __floats2half2_rn(lo, hi);   // low half = lo
    uint32_t u;
    memcpy(&u, &h, 4);
    return u;
}

// ---------------------------------------------------------------------------
// Prepass 1: W_dense [K,N] fp32 -> fp16 B-fragment pack.
// grid (N/16, NKS/8), 256 thr: thread = (ks_local = tid>>5, lane).
// ---------------------------------------------------------------------------
__global__ void __launch_bounds__(256)
pack_wd_kernel(const float* __restrict__ Wd) {
    const int nb16 = blockIdx.x;
    const int ks = blockIdx.y * 8 + (threadIdx.x >> 5);
    const int lane = threadIdx.x & 31;
    const int g = lane >> 2, t4 = lane & 3;
    const int k0 = ks * 16 + 2 * t4;
    const int n0 = nb16 * 16 + g;
    const float* p00 = Wd + (size_t)k0 * N_SZ + n0;
    uint4 v;
    v.x = h2pack(p00[0],              p00[N_SZ]);
    v.y = h2pack(p00[8 * N_SZ],       p00[9 * N_SZ]);
    v.z = h2pack(p00[8],              p00[N_SZ + 8]);
    v.w = h2pack(p00[8 * N_SZ + 8],   p00[9 * N_SZ + 8]);
    g_Bpack[((size_t)nb16 * NKS + ks) * 32 + lane] = v;
}

// ---------------------------------------------------------------------------
// Prepass 2: gather + bias -> fp16 A-fragment pack.
// Block = 128 M rows.  W_embed+bias as half2 LUT in smem; x rows staged in
// smem with bank-padded stride.
// ---------------------------------------------------------------------------
#define XS 260   // padded x-row stride in ints (260 % 32 = 4 -> g spreads banks)

__global__ void __launch_bounds__(256)
pack_a_kernel(const int* __restrict__ x, const float* __restrict__ We,
              const float* __restrict__ be) {
    __shared__ uint32_t sH[NCLS * 2];     // 8 KB: sH[cls*2+h] = half2(We[cls][2h]+be, We[cls][2h+1]+be)
    __shared__ int sX[16 * XS];           // 16.6 KB
    {
        const float be0 = be[0], be1 = be[1], be2 = be[2], be3 = be[3];
        for (int i = threadIdx.x; i < NCLS; i += 256) {
            const float4 e = *(const float4*)(We + i * 4);
            sH[i * 2]     = h2pack(e.x + be0, e.y + be1);
            sH[i * 2 + 1] = h2pack(e.z + be2, e.w + be3);
        }
    }
    const int tid = threadIdx.x;
    const int lane = tid & 31, w = tid >> 5;
    const int g = lane >> 2, t4 = lane & 3;
    const int h = t4 & 1, pq = t4 >> 1;
    const int rowbase = blockIdx.x * 128;

    for (int mb = 0; mb < 8; ++mb) {
        __syncthreads();
        // stage 16 rows of x (coalesced int4)
        {
            const int* src = x + (size_t)(rowbase + mb * 16) * P_SZ;
#pragma unroll
            for (int i = 0; i < 4; ++i) {
                const int cc = i * 256 + tid;          // 1024 int4
                const int row = cc >> 6, col4 = cc & 63;
                const int4 v = *(const int4*)(src + row * P_SZ + col4 * 4);
                *(int4*)(sX + row * XS + col4 * 4) = v;
            }
        }
        __syncthreads();
        const size_t mbG = (size_t)(rowbase >> 4) + mb;
#pragma unroll
        for (int kk = 0; kk < 8; ++kk) {
            const int ks = kk * 8 + w;
            const int p0 = ks * 4 + pq;
            const int x00 = sX[g * XS + p0];
            const int x10 = sX[(g + 8) * XS + p0];
            const int x01 = sX[g * XS + p0 + 2];
            const int x11 = sX[(g + 8) * XS + p0 + 2];
            uint4 v;
            v.x = sH[x00 * 2 + h];
            v.y = sH[x10 * 2 + h];
            v.z = sH[x01 * 2 + h];
            v.w = sH[x11 * 2 + h];
            g_Apack[(mbG * NKS + ks) * 32 + lane] = v;
        }
    }
}

// ---------------------------------------------------------------------------
// MMA: one k16-step = 16 HMMAs (2 m-tiles x 8 n-tiles).
// ---------------------------------------------------------------------------
__device__ __forceinline__ void mma_kstep(const uint4 a[2], const uint4 b[4],
                                          float c[2][8][4]) {
#pragma unroll
    for (int i4 = 0; i4 < 4; ++i4) {
#pragma unroll
        for (int i = 0; i < 2; ++i) {
            asm volatile(
                "mma.sync.aligned.m16n8k16.row.col.f32.f16.f16.f32 "
                "{%0,%1,%2,%3}, {%4,%5,%6,%7}, {%8,%9}, {%0,%1,%2,%3};"
                : "+f"(c[i][i4 * 2][0]), "+f"(c[i][i4 * 2][1]),
                  "+f"(c[i][i4 * 2][2]), "+f"(c[i][i4 * 2][3])
                : "r"(a[i].x), "r"(a[i].y), "r"(a[i].z), "r"(a[i].w),
                  "r"(b[i4].x), "r"(b[i4].y));
            asm volatile(
                "mma.sync.aligned.m16n8k16.row.col.f32.f16.f16.f32 "
                "{%0,%1,%2,%3}, {%4,%5,%6,%7}, {%8,%9}, {%0,%1,%2,%3};"
                : "+f"(c[i][i4 * 2 + 1][0]), "+f"(c[i][i4 * 2 + 1][1]),
                  "+f"(c[i][i4 * 2 + 1][2]), "+f"(c[i][i4 * 2 + 1][3])
                : "r"(a[i].x), "r"(a[i].y), "r"(a[i].z), "r"(a[i].w),
                  "r"(b[i4].z), "r"(b[i4].w));
        }
    }
}

// ---------------------------------------------------------------------------
// Main GEMM.  SMEM: 3 stages of [A 1024 u4 | B 1024 u4].
// Stage layout: A [mb][ksl][lane], B [nb16][ksl][lane].
// ---------------------------------------------------------------------------
__global__ void __launch_bounds__(THREADS, 2)
enc_gemm_kernel(const float* __restrict__ bd, float* __restrict__ out) {
    extern __shared__ uint4 smem[];
    const uint32_t sbase = smem_u32(smem);

    const int tid = threadIdx.x;
    const int wid = tid >> 5, lane = tid & 31;
    const int g = lane >> 2, t4 = lane & 3;
    const int warp_m = wid & 3;      // 4 x 32 = 128 M
    const int warp_n = wid >> 2;     // 2 x 64 = 128 N
    const int n0 = blockIdx.x * NT;
    const int m0 = blockIdx.y * MT;

    const uint4* asrc = g_Apack + (size_t)(m0 >> 4) * NKS * 32;
    const uint4* bsrc = g_Bpack + (size_t)(n0 >> 4) * NKS * 32;

    float c[2][8][4];
#pragma unroll
    for (int i = 0; i < 2; ++i)
#pragma unroll
        for (int j = 0; j < 8; ++j)
#pragma unroll
            for (int q = 0; q < 4; ++q) c[i][j][q] = 0.0f;

    auto stageA  = [&](int s) -> const uint4* { return smem + (size_t)s * STAGE_U4; };
    auto stageB  = [&](int s) -> const uint4* { return smem + (size_t)s * STAGE_U4 + A_U4; };
    auto stageAaddr = [&](int s) -> uint32_t { return sbase + (uint32_t)s * (STAGE_U4 * 16u); };
    auto stageBaddr = [&](int s) -> uint32_t { return sbase + (uint32_t)s * (STAGE_U4 * 16u) + A_U4 * 16u; };

    // per-chunk copy: A 1024 u4 + B 1024 u4 over 256 threads = 4+4 cp16 each
    auto copyAB = [&](int ch, int s) {
        const uint32_t aA = stageAaddr(s), bA = stageBaddr(s);
#pragma unroll
        for (int i = 0; i < 4; ++i) {
            const int cc = i * 256 + tid;
            const int mb = cc >> 7, rem = cc & 127;     // rem = ksl*32+lane
            cp16(aA + (uint32_t)cc * 16u,
                 asrc + ((size_t)mb * NKS + ch * KSC) * 32 + rem);
        }
#pragma unroll
        for (int i = 0; i < 4; ++i) {
            const int cc = i * 256 + tid;
            const int nb = cc >> 7, rem = cc & 127;
            cp16(bA + (uint32_t)cc * 16u,
                 bsrc + ((size_t)nb * NKS + ch * KSC) * 32 + rem);
        }
    };

    // ---- prologue ----
    copyAB(0, 0); CP_COMMIT();
    copyAB(1, 1); CP_COMMIT();

    // ---- mainloop ----
    for (int ch = 0; ch < NCHUNK; ++ch) {
        const int st = ch % 3;

        CP_WAIT1();              // stage st landed
        __syncthreads();         // stage (ch+2)%3 free

        if (ch + 2 < NCHUNK) copyAB(ch + 2, (ch + 2) % 3);
        CP_COMMIT();

        const uint4* aPtr = stageA(st) + (warp_m * 2) * (KSC * 32) + lane;
        const uint4* bPtr = stageB(st) + (warp_n * 4) * (KSC * 32) + lane;

#pragma unroll
        for (int ksl = 0; ksl < KSC; ++ksl) {
            uint4 a[2], b[4];
            a[0] = aPtr[ksl * 32];
            a[1] = aPtr[KSC * 32 + ksl * 32];
#pragma unroll
            for (int i = 0; i < 4; ++i)
                b[i] = bPtr[i * (KSC * 32) + ksl * 32];
            mma_kstep(a, b, c);
        }
    }

    // ---- epilogue: accum + b_dense -> out ----
#pragma unroll
    for (int i = 0; i < 2; ++i) {
        const size_t r0 = (size_t)(m0 + warp_m * 32 + i * 16 + g);
#pragma unroll
        for (int j = 0; j < 8; ++j) {
            const int col = n0 + warp_n * 64 + j * 8 + t4 * 2;
            const float2 bb = *(const float2*)(bd + col);
            float2 v0, v1;
            v0.x = c[i][j][0] + bb.x;  v0.y = c[i][j][1] + bb.y;
            v1.x = c[i][j][2] + bb.x;  v1.y = c[i][j][3] + bb.y;
            *(float2*)(out + r0 * N_SZ + col)       = v0;
            *(float2*)(out + (r0 + 8) * N_SZ + col) = v1;
        }
    }
}

// ---------------------------------------------------------------------------
// kernel_launch
// ---------------------------------------------------------------------------
extern "C" void kernel_launch(void* const* d_in, const int* in_sizes, int n_in,
                              void* d_out, int out_size) {
    const int*   x  = (const int*)d_in[0];
    const float* We = (const float*)d_in[1];
    const float* be = (const float*)d_in[2];
    const float* Wd = (const float*)d_in[3];
    const float* bd = (const float*)d_in[4];
    float* out = (float*)d_out;

    cudaStreamCaptureStatus cs = cudaStreamCaptureStatusNone;
    cudaError_t qerr = cudaStreamIsCapturing((cudaStream_t)0, &cs);
    const bool capturing = (qerr != cudaSuccess) || (cs != cudaStreamCaptureStatusNone);
    if (!capturing) {
        cudaFuncSetAttribute(enc_gemm_kernel,
                             cudaFuncAttributeMaxDynamicSharedMemorySize, SMEM_BYTES);
    }
    (void)cudaGetLastError();

    pack_wd_kernel<<<dim3(N_SZ / 16, NKS / 8), 256>>>(Wd);
    pack_a_kernel<<<B_SZ / 128, 256>>>(x, We, be);
    enc_gemm_kernel<<<dim3(N_SZ / NT, B_SZ / MT), THREADS, SMEM_BYTES>>>(bd, out);
}